// round 1
// baseline (speedup 1.0000x reference)
#include <cuda_runtime.h>
#include <cstdint>

#define NB 2
#define NL 32
#define NC 32
#define NN 8192
#define NSPLIT 8
#define JCHUNK (NN / NSPLIT)
#define TJ 128
#define ROWS 128

typedef unsigned long long u64;

// -------- scratch (device globals; no allocation allowed) --------
__device__ float g_Q[NB][NN][16];            // 1 MB
__device__ float g_V[NB][NN][32];            // 2 MB
__device__ float g_Rn[NB][NN];               // per-row |Q_i|^2
__device__ int   g_Msq[NB];                  // max |Q_j|^2 per batch (float bits)
__device__ float g_Part[NB][NSPLIT][33][NN]; // split partials: 32 acc channels + l

// -------- packed f32x2 helpers (FFMA2 on sm_103a) --------
__device__ __forceinline__ u64 f2_fma(u64 a, u64 b, u64 c) {
    u64 d; asm("fma.rn.f32x2 %0, %1, %2, %3;" : "=l"(d) : "l"(a), "l"(b), "l"(c)); return d;
}
__device__ __forceinline__ u64 f2_mul(u64 a, u64 b) {
    u64 d; asm("mul.rn.f32x2 %0, %1, %2;" : "=l"(d) : "l"(a), "l"(b)); return d;
}
__device__ __forceinline__ u64 f2_add(u64 a, u64 b) {
    u64 d; asm("add.rn.f32x2 %0, %1, %2;" : "=l"(d) : "l"(a), "l"(b)); return d;
}
__device__ __forceinline__ u64 f2_pack(float lo, float hi) {
    u64 d; asm("mov.b64 %0, {%1, %2};" : "=l"(d) : "f"(lo), "f"(hi)); return d;
}
__device__ __forceinline__ float2 f2_unpack(u64 v) {
    float lo, hi; asm("mov.b64 {%0, %1}, %2;" : "=f"(lo), "=f"(hi) : "l"(v));
    return make_float2(lo, hi);
}

// -------- kernel 0: reset per-batch max --------
__global__ void init_kernel() {
    if (threadIdx.x < NB) g_Msq[threadIdx.x] = 0;
}

// -------- kernel 1: compute Q [b,i,16], V [b,j,32], row norms, global max --------
// One block per (b, hw). X = inp[b,:,h,w,:] is a 32x32 tile.
__global__ void __launch_bounds__(128) qv_kernel(
    const float* __restrict__ inp, const float* __restrict__ W1,
    const float* __restrict__ b1,  const float* __restrict__ W2,
    const float* __restrict__ b2)
{
    __shared__ float Xs[NL][NC];
    __shared__ float W1s[16][32];
    __shared__ float W2s[32][32];
    __shared__ float b1s[16];
    __shared__ float b2s[32];
    __shared__ float Aq[32][16];   // Q rows of this block, for norm reduce

    int b  = blockIdx.x >> 8;
    int hw = blockIdx.x & 255;
    int tid = threadIdx.x;

    const float* ib = inp + (size_t)b * 262144 + hw * 32;
    for (int idx = tid; idx < 1024; idx += 128) {
        int l = idx >> 5, c = idx & 31;
        Xs[l][c] = ib[l * 8192 + c];
    }
    for (int idx = tid; idx < 512;  idx += 128) W1s[idx >> 5][idx & 31] = W1[idx];
    for (int idx = tid; idx < 1024; idx += 128) W2s[idx >> 5][idx & 31] = W2[idx];
    if (tid < 16) b1s[tid] = b1[tid];
    if (tid >= 32 && tid < 64) b2s[tid - 32] = b2[tid - 32];
    __syncthreads();

    // V[b, o*256+hw, c] = b2[o] + sum_l W2[o,l] * X[l,c]
    for (int idx = tid; idx < 1024; idx += 128) {
        int o = idx >> 5, c = idx & 31;
        float s = b2s[o];
        #pragma unroll
        for (int l = 0; l < 32; l++) s += W2s[o][l] * Xs[l][c];
        g_V[b][o * 256 + hw][c] = s;
    }
    // Q[b, i12*4096 + o*256 + hw, k] = b1[o] + sum_l W1[o,l] * X[l, 2k+i12]
    for (int idx = tid; idx < 512; idx += 128) {
        int o = idx >> 5, ch = idx & 31;
        float s = b1s[o];
        #pragma unroll
        for (int l = 0; l < 32; l++) s += W1s[o][l] * Xs[l][ch];
        int k = ch >> 1, i12 = ch & 1;
        g_Q[b][i12 * 4096 + o * 256 + hw][k] = s;
        Aq[(o << 1) | i12][k] = s;
    }
    __syncthreads();

    if (tid < 32) {
        int o = tid >> 1, i12 = tid & 1;
        float s = 0.f;
        #pragma unroll
        for (int k = 0; k < 16; k++) { float v = Aq[tid][k]; s += v * v; }
        g_Rn[b][i12 * 4096 + o * 256 + hw] = s;
        atomicMax(&g_Msq[b], __float_as_int(s));  // valid for nonneg floats
    }
}

// -------- kernel 2: flash attention partials over a j-split --------
// Exact softmax via fixed shift m_hat = |Q_i| * max_j|Q_j| >= all logits,
// so split partials (acc, l) add directly in the combine step.
__global__ void __launch_bounds__(128) attn_kernel() {
    __shared__ __align__(16) float Ks[TJ][16];
    __shared__ __align__(16) float Vs[TJ][32];

    int b   = blockIdx.z;
    int sp  = blockIdx.y;
    int tid = threadIdx.x;
    int i   = blockIdx.x * ROWS + tid;

    const ulonglong2* qr = (const ulonglong2*)&g_Q[b][i][0];
    ulonglong2 qA = qr[0], qB = qr[1], qC = qr[2], qD = qr[3];
    float mhat = sqrtf(g_Rn[b][i] * __int_as_float(g_Msq[b]));
    float lsum = 0.f;
    u64 acc[16];
    #pragma unroll
    for (int t = 0; t < 16; t++) acc[t] = 0ULL;

    int j0 = sp * JCHUNK;
    for (int jt = 0; jt < JCHUNK; jt += TJ) {
        const float4* gk = (const float4*)&g_Q[b][j0 + jt][0];
        const float4* gv = (const float4*)&g_V[b][j0 + jt][0];
        #pragma unroll
        for (int u = 0; u < 4; u++) ((float4*)Ks)[tid + 128 * u] = gk[tid + 128 * u];
        #pragma unroll
        for (int u = 0; u < 8; u++) ((float4*)Vs)[tid + 128 * u] = gv[tid + 128 * u];
        __syncthreads();

        #pragma unroll 2
        for (int j = 0; j < TJ; j++) {
            // dot(Q_i, K_j), 16 elements via 8 FFMA2-class ops (all lanes same j => LDS broadcast)
            const ulonglong2* kr = (const ulonglong2*)Ks[j];
            ulonglong2 k0 = kr[0], k1 = kr[1], k2 = kr[2], k3 = kr[3];
            u64 sa = f2_mul(k0.x, qA.x);
            u64 sb = f2_mul(k0.y, qA.y);
            sa = f2_fma(k1.x, qB.x, sa);
            sb = f2_fma(k1.y, qB.y, sb);
            sa = f2_fma(k2.x, qC.x, sa);
            sb = f2_fma(k2.y, qC.y, sb);
            sa = f2_fma(k3.x, qD.x, sa);
            sb = f2_fma(k3.y, qD.y, sb);
            sa = f2_add(sa, sb);
            float2 sf = f2_unpack(sa);
            float p = __expf(sf.x + sf.y - mhat);   // arg <= 0, no overflow; underflow harmless
            lsum += p;
            u64 pp = f2_pack(p, p);
            const ulonglong2* vr = (const ulonglong2*)Vs[j];
            #pragma unroll
            for (int t = 0; t < 8; t++) {
                ulonglong2 vv = vr[t];
                acc[2 * t]     = f2_fma(vv.x, pp, acc[2 * t]);
                acc[2 * t + 1] = f2_fma(vv.y, pp, acc[2 * t + 1]);
            }
        }
        __syncthreads();
    }

    #pragma unroll
    for (int t = 0; t < 16; t++) {
        float2 f = f2_unpack(acc[t]);
        g_Part[b][sp][2 * t][i]     = f.x;   // coalesced: consecutive tid -> consecutive i
        g_Part[b][sp][2 * t + 1][i] = f.y;
    }
    g_Part[b][sp][32][i] = lsum;
}

// -------- kernel 3: combine splits, normalize, residual add --------
__global__ void combine_kernel(const float* __restrict__ inp,
                               const float* __restrict__ gamma,
                               float* __restrict__ out)
{
    int tid = blockIdx.x * blockDim.x + threadIdx.x;   // 524288 threads
    int b = tid >> 18;
    int r = tid & 262143;
    int c = r >> 13;        // 0..31
    int i = r & 8191;       // 0..8191 (inner => coalesced Part reads)
    float a = 0.f, l = 0.f;
    #pragma unroll
    for (int s = 0; s < NSPLIT; s++) {
        a += g_Part[b][s][c][i];
        l += g_Part[b][s][32][i];
    }
    int o = b * 262144 + i * 32 + c;  // out[b, l, h, w, c] with i = l*256+h*16+w
    out[o] = a / l * gamma[0] + inp[o];
}

extern "C" void kernel_launch(void* const* d_in, const int* in_sizes, int n_in,
                              void* d_out, int out_size) {
    const float* inp   = (const float*)d_in[0];
    const float* W1    = (const float*)d_in[1];
    const float* b1    = (const float*)d_in[2];
    const float* W2    = (const float*)d_in[3];
    const float* b2    = (const float*)d_in[4];
    const float* gamma = (const float*)d_in[5];
    float* out = (float*)d_out;

    init_kernel<<<1, 32>>>();
    qv_kernel<<<NB * 256, 128>>>(inp, W1, b1, W2, b2);
    attn_kernel<<<dim3(NN / ROWS, NSPLIT, NB), 128>>>();
    combine_kernel<<<(NB * NN * 32) / 256, 256>>>(inp, gamma, out);
}

// round 2
// speedup vs baseline: 1.0014x; 1.0014x over previous
#include <cuda_runtime.h>
#include <cstdint>

#define NB 2
#define NL 32
#define NC 32
#define NN 8192
#define NSPLIT 8
#define JCHUNK (NN / NSPLIT)
#define TJ 128
#define ROWS 128

typedef unsigned long long u64;

// -------- scratch (device globals; no allocation allowed) --------
__device__ float g_Q[NB][NN][16];            // 1 MB
__device__ float g_V[NB][NN][32];            // 2 MB
__device__ float g_Rn[NB][NN];               // per-row |Q_i|^2
__device__ int   g_Msq[NB];                  // max |Q_j|^2 per batch (float bits)
__device__ float g_Part[NB][NSPLIT][33][NN]; // split partials: 32 acc channels + l

// -------- packed f32x2 helpers (FFMA2 on sm_103a) --------
__device__ __forceinline__ u64 f2_fma(u64 a, u64 b, u64 c) {
    u64 d; asm("fma.rn.f32x2 %0, %1, %2, %3;" : "=l"(d) : "l"(a), "l"(b), "l"(c)); return d;
}
__device__ __forceinline__ u64 f2_mul(u64 a, u64 b) {
    u64 d; asm("mul.rn.f32x2 %0, %1, %2;" : "=l"(d) : "l"(a), "l"(b)); return d;
}
__device__ __forceinline__ u64 f2_add(u64 a, u64 b) {
    u64 d; asm("add.rn.f32x2 %0, %1, %2;" : "=l"(d) : "l"(a), "l"(b)); return d;
}
__device__ __forceinline__ u64 f2_pack(float lo, float hi) {
    u64 d; asm("mov.b64 %0, {%1, %2};" : "=l"(d) : "f"(lo), "f"(hi)); return d;
}
__device__ __forceinline__ float2 f2_unpack(u64 v) {
    float lo, hi; asm("mov.b64 {%0, %1}, %2;" : "=f"(lo), "=f"(hi) : "l"(v));
    return make_float2(lo, hi);
}

// -------- kernel 0: reset per-batch max --------
__global__ void init_kernel() {
    if (threadIdx.x < NB) g_Msq[threadIdx.x] = 0;
}

// -------- kernel 1: compute Q [b,i,16], V [b,j,32], row norms, global max --------
// One block per (b, hw). X = inp[b,:,h,w,:] is a 32x32 tile.
__global__ void __launch_bounds__(128) qv_kernel(
    const float* __restrict__ inp, const float* __restrict__ W1,
    const float* __restrict__ b1,  const float* __restrict__ W2,
    const float* __restrict__ b2)
{
    __shared__ float Xs[NL][NC];
    __shared__ float W1s[16][32];
    __shared__ float W2s[32][32];
    __shared__ float b1s[16];
    __shared__ float b2s[32];
    __shared__ float Aq[32][16];   // Q rows of this block, for norm reduce

    int b  = blockIdx.x >> 8;
    int hw = blockIdx.x & 255;
    int tid = threadIdx.x;

    const float* ib = inp + (size_t)b * 262144 + hw * 32;
    for (int idx = tid; idx < 1024; idx += 128) {
        int l = idx >> 5, c = idx & 31;
        Xs[l][c] = ib[l * 8192 + c];
    }
    for (int idx = tid; idx < 512;  idx += 128) W1s[idx >> 5][idx & 31] = W1[idx];
    for (int idx = tid; idx < 1024; idx += 128) W2s[idx >> 5][idx & 31] = W2[idx];
    if (tid < 16) b1s[tid] = b1[tid];
    if (tid >= 32 && tid < 64) b2s[tid - 32] = b2[tid - 32];
    __syncthreads();

    // V[b, o*256+hw, c] = b2[o] + sum_l W2[o,l] * X[l,c]
    for (int idx = tid; idx < 1024; idx += 128) {
        int o = idx >> 5, c = idx & 31;
        float s = b2s[o];
        #pragma unroll
        for (int l = 0; l < 32; l++) s += W2s[o][l] * Xs[l][c];
        g_V[b][o * 256 + hw][c] = s;
    }
    // Q[b, i12*4096 + o*256 + hw, k] = b1[o] + sum_l W1[o,l] * X[l, 2k+i12]
    for (int idx = tid; idx < 512; idx += 128) {
        int o = idx >> 5, ch = idx & 31;
        float s = b1s[o];
        #pragma unroll
        for (int l = 0; l < 32; l++) s += W1s[o][l] * Xs[l][ch];
        int k = ch >> 1, i12 = ch & 1;
        g_Q[b][i12 * 4096 + o * 256 + hw][k] = s;
        Aq[(o << 1) | i12][k] = s;
    }
    __syncthreads();

    if (tid < 32) {
        int o = tid >> 1, i12 = tid & 1;
        float s = 0.f;
        #pragma unroll
        for (int k = 0; k < 16; k++) { float v = Aq[tid][k]; s += v * v; }
        g_Rn[b][i12 * 4096 + o * 256 + hw] = s;
        atomicMax(&g_Msq[b], __float_as_int(s));  // valid for nonneg floats
    }
}

// -------- kernel 2: flash attention partials over a j-split --------
// Exact softmax via fixed shift m_hat = |Q_i| * max_j|Q_j| >= all logits,
// so split partials (acc, l) add directly in the combine step.
__global__ void __launch_bounds__(128) attn_kernel() {
    __shared__ __align__(16) float Ks[TJ][16];
    __shared__ __align__(16) float Vs[TJ][32];

    int b   = blockIdx.z;
    int sp  = blockIdx.y;
    int tid = threadIdx.x;
    int i   = blockIdx.x * ROWS + tid;

    const ulonglong2* qr = (const ulonglong2*)&g_Q[b][i][0];
    ulonglong2 qA = qr[0], qB = qr[1], qC = qr[2], qD = qr[3];
    float mhat = sqrtf(g_Rn[b][i] * __int_as_float(g_Msq[b]));
    float lsum = 0.f;
    u64 acc[16];
    #pragma unroll
    for (int t = 0; t < 16; t++) acc[t] = 0ULL;

    int j0 = sp * JCHUNK;
    for (int jt = 0; jt < JCHUNK; jt += TJ) {
        const float4* gk = (const float4*)&g_Q[b][j0 + jt][0];
        const float4* gv = (const float4*)&g_V[b][j0 + jt][0];
        #pragma unroll
        for (int u = 0; u < 4; u++) ((float4*)Ks)[tid + 128 * u] = gk[tid + 128 * u];
        #pragma unroll
        for (int u = 0; u < 8; u++) ((float4*)Vs)[tid + 128 * u] = gv[tid + 128 * u];
        __syncthreads();

        #pragma unroll 2
        for (int j = 0; j < TJ; j++) {
            // dot(Q_i, K_j), 16 elements via 8 FFMA2-class ops (all lanes same j => LDS broadcast)
            const ulonglong2* kr = (const ulonglong2*)Ks[j];
            ulonglong2 k0 = kr[0], k1 = kr[1], k2 = kr[2], k3 = kr[3];
            u64 sa = f2_mul(k0.x, qA.x);
            u64 sb = f2_mul(k0.y, qA.y);
            sa = f2_fma(k1.x, qB.x, sa);
            sb = f2_fma(k1.y, qB.y, sb);
            sa = f2_fma(k2.x, qC.x, sa);
            sb = f2_fma(k2.y, qC.y, sb);
            sa = f2_fma(k3.x, qD.x, sa);
            sb = f2_fma(k3.y, qD.y, sb);
            sa = f2_add(sa, sb);
            float2 sf = f2_unpack(sa);
            float p = __expf(sf.x + sf.y - mhat);   // arg <= 0, no overflow; underflow harmless
            lsum += p;
            u64 pp = f2_pack(p, p);
            const ulonglong2* vr = (const ulonglong2*)Vs[j];
            #pragma unroll
            for (int t = 0; t < 8; t++) {
                ulonglong2 vv = vr[t];
                acc[2 * t]     = f2_fma(vv.x, pp, acc[2 * t]);
                acc[2 * t + 1] = f2_fma(vv.y, pp, acc[2 * t + 1]);
            }
        }
        __syncthreads();
    }

    #pragma unroll
    for (int t = 0; t < 16; t++) {
        float2 f = f2_unpack(acc[t]);
        g_Part[b][sp][2 * t][i]     = f.x;   // coalesced: consecutive tid -> consecutive i
        g_Part[b][sp][2 * t + 1][i] = f.y;
    }
    g_Part[b][sp][32][i] = lsum;
}

// -------- kernel 3: combine splits, normalize, residual add --------
__global__ void combine_kernel(const float* __restrict__ inp,
                               const float* __restrict__ gamma,
                               float* __restrict__ out)
{
    int tid = blockIdx.x * blockDim.x + threadIdx.x;   // 524288 threads
    int b = tid >> 18;
    int r = tid & 262143;
    int c = r >> 13;        // 0..31
    int i = r & 8191;       // 0..8191 (inner => coalesced Part reads)
    float a = 0.f, l = 0.f;
    #pragma unroll
    for (int s = 0; s < NSPLIT; s++) {
        a += g_Part[b][s][c][i];
        l += g_Part[b][s][32][i];
    }
    int o = b * 262144 + i * 32 + c;  // out[b, l, h, w, c] with i = l*256+h*16+w
    out[o] = a / l * gamma[0] + inp[o];
}

extern "C" void kernel_launch(void* const* d_in, const int* in_sizes, int n_in,
                              void* d_out, int out_size) {
    const float* inp   = (const float*)d_in[0];
    const float* W1    = (const float*)d_in[1];
    const float* b1    = (const float*)d_in[2];
    const float* W2    = (const float*)d_in[3];
    const float* b2    = (const float*)d_in[4];
    const float* gamma = (const float*)d_in[5];
    float* out = (float*)d_out;

    init_kernel<<<1, 32>>>();
    qv_kernel<<<NB * 256, 128>>>(inp, W1, b1, W2, b2);
    attn_kernel<<<dim3(NN / ROWS, NSPLIT, NB), 128>>>();
    combine_kernel<<<(NB * NN * 32) / 256, 256>>>(inp, gamma, out);
}

// round 4
// speedup vs baseline: 5.7123x; 5.7045x over previous
#include <cuda_runtime.h>
#include <cuda_fp16.h>
#include <cstdint>

#define NB 2
#define NN 8192
#define BM 128
#define NTILES 64
#define L2E 1.4426950408889634f

// -------- scratch (device globals; no allocation allowed) --------
__device__ __align__(16) __half g_Qh[NB][NN][16];  // fp16 Q (= K), 0.5 MB
__device__ __align__(16) __half g_Vh[NB][NN][32];  // fp16 V, 1 MB
__device__ float g_Rn[NB][NN];                     // |Q_i|^2 (fp32)
__device__ int   g_Msq[NB];                        // max |Q_j|^2 (float bits)

// ---------------- helpers ----------------
__device__ __forceinline__ uint32_t smem_u32(const void* p) {
    uint32_t a;
    asm("{ .reg .u64 t; cvta.to.shared.u64 t, %1; cvt.u32.u64 %0, t; }" : "=r"(a) : "l"(p));
    return a;
}
__device__ __forceinline__ void ldsm4(uint32_t* r, uint32_t a) {
    asm volatile("ldmatrix.sync.aligned.m8n8.x4.shared.b16 {%0,%1,%2,%3}, [%4];"
        : "=r"(r[0]), "=r"(r[1]), "=r"(r[2]), "=r"(r[3]) : "r"(a));
}
__device__ __forceinline__ void ldsm4t(uint32_t* r, uint32_t a) {
    asm volatile("ldmatrix.sync.aligned.m8n8.x4.trans.shared.b16 {%0,%1,%2,%3}, [%4];"
        : "=r"(r[0]), "=r"(r[1]), "=r"(r[2]), "=r"(r[3]) : "r"(a));
}
__device__ __forceinline__ void mma16816(float* d, const uint32_t* a, uint32_t b0, uint32_t b1) {
    asm volatile("mma.sync.aligned.m16n8k16.row.col.f32.f16.f16.f32 "
        "{%0,%1,%2,%3}, {%4,%5,%6,%7}, {%8,%9}, {%0,%1,%2,%3};"
        : "+f"(d[0]), "+f"(d[1]), "+f"(d[2]), "+f"(d[3])
        : "r"(a[0]), "r"(a[1]), "r"(a[2]), "r"(a[3]), "r"(b0), "r"(b1));
}
__device__ __forceinline__ float ex2f(float x) {
    float r; asm("ex2.approx.f32 %0, %1;" : "=f"(r) : "f"(x)); return r;
}
__device__ __forceinline__ uint32_t pack2(float a, float b) {
    __half2 h = __floats2half2_rn(a, b);
    return *(uint32_t*)&h;
}

// -------- kernel 0 --------
__global__ void init_kernel() { if (threadIdx.x < NB) g_Msq[threadIdx.x] = 0; }

// -------- kernel 1: Q (fp16), V (fp16), row norms, global max --------
__global__ void __launch_bounds__(128) qv_kernel(
    const float* __restrict__ inp, const float* __restrict__ W1,
    const float* __restrict__ b1,  const float* __restrict__ W2,
    const float* __restrict__ b2)
{
    __shared__ float Xs[32][32];
    __shared__ float W1s[16][32];
    __shared__ float W2s[32][32];
    __shared__ float b1s[16];
    __shared__ float b2s[32];
    __shared__ float Aq[32][16];

    int b  = blockIdx.x >> 8;
    int hw = blockIdx.x & 255;
    int tid = threadIdx.x;

    const float* ib = inp + (size_t)b * 262144 + hw * 32;
    for (int idx = tid; idx < 1024; idx += 128) {
        int l = idx >> 5, c = idx & 31;
        Xs[l][c] = ib[l * 8192 + c];
    }
    for (int idx = tid; idx < 512;  idx += 128) W1s[idx >> 5][idx & 31] = W1[idx];
    for (int idx = tid; idx < 1024; idx += 128) W2s[idx >> 5][idx & 31] = W2[idx];
    if (tid < 16) b1s[tid] = b1[tid];
    if (tid >= 32 && tid < 64) b2s[tid - 32] = b2[tid - 32];
    __syncthreads();

    // V[b, o*256+hw, c]
    for (int idx = tid; idx < 1024; idx += 128) {
        int o = idx >> 5, c = idx & 31;
        float s = b2s[o];
        #pragma unroll
        for (int l = 0; l < 32; l++) s += W2s[o][l] * Xs[l][c];
        g_Vh[b][o * 256 + hw][c] = __float2half(s);
    }
    // Q[b, i12*4096 + o*256 + hw, k]
    for (int idx = tid; idx < 512; idx += 128) {
        int o = idx >> 5, ch = idx & 31;
        float s = b1s[o];
        #pragma unroll
        for (int l = 0; l < 32; l++) s += W1s[o][l] * Xs[l][ch];
        int k = ch >> 1, i12 = ch & 1;
        g_Qh[b][i12 * 4096 + o * 256 + hw][k] = __float2half(s);
        Aq[(o << 1) | i12][k] = s;
    }
    __syncthreads();

    if (tid < 32) {
        int o = tid >> 1, i12 = tid & 1;
        float s = 0.f;
        #pragma unroll
        for (int k = 0; k < 16; k++) { float v = Aq[tid][k]; s += v * v; }
        g_Rn[b][i12 * 4096 + o * 256 + hw] = s;
        atomicMax(&g_Msq[b], __float_as_int(s));
    }
}

// -------- kernel 2: FA2-style fp16 mma.sync attention --------
// Fixed-shift softmax: m_hat_i = |Q_i| * max_j |Q_j| >= all logits (exact bound).
__global__ void __launch_bounds__(256, 1) attn3_kernel(
    const float* __restrict__ inp, const float* __restrict__ gamma,
    float* __restrict__ out)
{
    // XOR-swizzled tiles (16B segment granularity)
    __shared__ __align__(16) __half Qs[BM * 16];        // 4 KB
    __shared__ __align__(16) __half Ks[2][BM * 16];     // 2x4 KB
    __shared__ __align__(16) __half Vs[2][BM * 32];     // 2x8 KB

    int tid = threadIdx.x, lane = tid & 31, wid = tid >> 5;
    int b = blockIdx.y;
    int i0 = blockIdx.x * BM;
    int wrow = wid * 16;

    // ---- preload Q tile and tile-0 K/V ----
    {   // Q + K: 256 uint4 each; row=e>>1 (32B rows), seg=e&1; swz: seg^((row>>2)&1)
        int r = tid >> 1, s = tid & 1;
        int sw = s ^ ((r >> 2) & 1);
        ((uint4*)Qs)[r * 2 + sw]    = *(const uint4*)&g_Qh[b][i0 + r][s * 8];
        ((uint4*)Ks[0])[r * 2 + sw] = *(const uint4*)&g_Qh[b][r][s * 8];
    }
    #pragma unroll
    for (int u = 0; u < 2; u++) {   // V: 512 uint4; row=e>>2 (64B rows), seg=e&3; swz: seg^((row>>1)&3)
        int e = tid + 256 * u;
        int r = e >> 2, s = e & 3;
        ((uint4*)Vs[0])[r * 4 + (s ^ ((r >> 1) & 3))] = *(const uint4*)&g_Vh[b][r][s * 8];
    }
    __syncthreads();

    // ---- Q A-fragments (once) ----
    uint32_t qa[4];
    {
        int row = wrow + (lane & 7) + (lane & 8);
        int seg = lane >> 4;
        uint32_t a = smem_u32(Qs) + row * 32 + (seg ^ ((row >> 2) & 1)) * 16;
        ldsm4(qa, a);
    }

    float msq = __int_as_float(g_Msq[b]);
    int ia = i0 + wrow + (lane >> 2);
    float mh2a = L2E * sqrtf(g_Rn[b][ia] * msq);
    float mh2b = L2E * sqrtf(g_Rn[b][ia + 8] * msq);

    float Dc[16];
    #pragma unroll
    for (int t = 0; t < 16; t++) Dc[t] = 0.f;
    float lsa = 0.f, lsb = 0.f;
    uint32_t pA[8][4];

    uint32_t kbase0 = smem_u32(Ks[0]), kbase1 = smem_u32(Ks[1]);
    uint32_t vbase0 = smem_u32(Vs[0]), vbase1 = smem_u32(Vs[1]);

    for (int t = 0; t < NTILES; t++) {
        // prefetch next tile (gmem -> regs)
        uint4 kpre, vp0, vp1;
        if (t < NTILES - 1) {
            int jb2 = (t + 1) * BM;
            kpre = *(const uint4*)&g_Qh[b][jb2 + (tid >> 1)][(tid & 1) * 8];
            vp0  = *(const uint4*)&g_Vh[b][jb2 + (tid >> 2)][(tid & 3) * 8];
            int e = tid + 256;
            vp1  = *(const uint4*)&g_Vh[b][jb2 + (e >> 2)][(e & 3) * 8];
        }

        uint32_t kb = (t & 1) ? kbase1 : kbase0;
        uint32_t vb = (t & 1) ? vbase1 : vbase0;

        // ---- S = Q K^T (per n-pair), epilogue fused ----
        #pragma unroll
        for (int np = 0; np < 8; np++) {
            uint32_t kf[4];
            {   // non-trans: B frags for n = j cols; mat0/1: rows np*16+(0..7) seg0/1; mat2/3: rows+8
                int row = np * 16 + (lane & 7) + ((lane >> 4) << 3);
                int seg = (lane >> 3) & 1;
                ldsm4(kf, kb + row * 32 + (seg ^ ((row >> 2) & 1)) * 16);
            }
            float s0[4] = {0.f, 0.f, 0.f, 0.f};
            mma16816(s0, qa, kf[0], kf[1]);
            float p0 = ex2f(fmaf(s0[0], L2E, -mh2a));
            float p1 = ex2f(fmaf(s0[1], L2E, -mh2a));
            float p2 = ex2f(fmaf(s0[2], L2E, -mh2b));
            float p3 = ex2f(fmaf(s0[3], L2E, -mh2b));
            lsa += p0 + p1; lsb += p2 + p3;
            pA[np][0] = pack2(p0, p1);
            pA[np][1] = pack2(p2, p3);

            float s1[4] = {0.f, 0.f, 0.f, 0.f};
            mma16816(s1, qa, kf[2], kf[3]);
            p0 = ex2f(fmaf(s1[0], L2E, -mh2a));
            p1 = ex2f(fmaf(s1[1], L2E, -mh2a));
            p2 = ex2f(fmaf(s1[2], L2E, -mh2b));
            p3 = ex2f(fmaf(s1[3], L2E, -mh2b));
            lsa += p0 + p1; lsb += p2 + p3;
            pA[np][2] = pack2(p0, p1);
            pA[np][3] = pack2(p2, p3);
        }

        // ---- D += P V ----
        #pragma unroll
        for (int ks = 0; ks < 8; ks++) {
            #pragma unroll
            for (int npair = 0; npair < 2; npair++) {
                uint32_t vf[4];
                {   // trans: mat0: rows 16ks+(0..7) seg 2npair; mat1: rows+8; mat2/3: seg+1
                    int row = 16 * ks + (lane & 7) + (((lane >> 3) & 1) << 3);
                    int seg = npair * 2 + ((lane >> 4) & 1);
                    ldsm4t(vf, vb + row * 64 + (seg ^ ((row >> 1) & 3)) * 16);
                }
                mma16816(Dc + (2 * npair) * 4,     pA[ks], vf[0], vf[1]);
                mma16816(Dc + (2 * npair + 1) * 4, pA[ks], vf[2], vf[3]);
            }
        }

        // ---- stage next tile into the other buffer ----
        if (t < NTILES - 1) {
            int nxt = (t + 1) & 1;
            int r = tid >> 1, s = tid & 1;
            ((uint4*)Ks[nxt])[r * 2 + (s ^ ((r >> 2) & 1))] = kpre;
            r = tid >> 2; s = tid & 3;
            ((uint4*)Vs[nxt])[r * 4 + (s ^ ((r >> 1) & 3))] = vp0;
            int e = tid + 256;
            r = e >> 2; s = e & 3;
            ((uint4*)Vs[nxt])[r * 4 + (s ^ ((r >> 1) & 3))] = vp1;
        }
        __syncthreads();
    }

    // ---- reduce row sums across quads, normalize, residual, write ----
    lsa += __shfl_xor_sync(0xffffffffu, lsa, 1);
    lsa += __shfl_xor_sync(0xffffffffu, lsa, 2);
    lsb += __shfl_xor_sync(0xffffffffu, lsb, 1);
    lsb += __shfl_xor_sync(0xffffffffu, lsb, 2);

    float g = gamma[0];
    float ra = g / lsa, rb = g / lsb;
    size_t ba = (size_t)b * 262144 + (size_t)ia * 32;
    size_t bb = ba + 8 * 32;
    #pragma unroll
    for (int nt = 0; nt < 4; nt++) {
        int col = nt * 8 + (lane & 3) * 2;
        float2 iv = *(const float2*)(inp + ba + col);
        float2 ov;
        ov.x = Dc[nt * 4 + 0] * ra + iv.x;
        ov.y = Dc[nt * 4 + 1] * ra + iv.y;
        *(float2*)(out + ba + col) = ov;
        iv = *(const float2*)(inp + bb + col);
        ov.x = Dc[nt * 4 + 2] * rb + iv.x;
        ov.y = Dc[nt * 4 + 3] * rb + iv.y;
        *(float2*)(out + bb + col) = ov;
    }
}

extern "C" void kernel_launch(void* const* d_in, const int* in_sizes, int n_in,
                              void* d_out, int out_size) {
    const float* inp   = (const float*)d_in[0];
    const float* W1    = (const float*)d_in[1];
    const float* b1    = (const float*)d_in[2];
    const float* W2    = (const float*)d_in[3];
    const float* b2    = (const float*)d_in[4];
    const float* gamma = (const float*)d_in[5];
    float* out = (float*)d_out;

    init_kernel<<<1, 32>>>();
    qv_kernel<<<NB * 256, 128>>>(inp, W1, b1, W2, b2);
    attn3_kernel<<<dim3(NN / BM, NB), 256>>>(inp, gamma, out);
}

// round 5
// speedup vs baseline: 6.9739x; 1.2209x over previous
#include <cuda_runtime.h>
#include <cuda_fp16.h>
#include <cstdint>

#define NB 2
#define NN 8192
#define BM 128
#define NTILES 64
#define L2E 1.4426950408889634f

// -------- scratch (device globals; no allocation allowed) --------
__device__ __align__(16) __half g_Qh[NB][NN][16];  // fp16 Q, pre-scaled by log2e (A side)
__device__ __align__(16) __half g_Kh[NB][NN][16];  // fp16 K, unscaled (B side)
__device__ __align__(16) __half g_Vh[NB][NN][32];  // fp16 V
__device__ float g_Rn[NB][NN];                     // |Q_i|^2 (fp32, unscaled)
__device__ float g_bmax[NB][256];                  // per-block max |Q|^2 (no reset needed)

// ---------------- helpers ----------------
__device__ __forceinline__ uint32_t smem_u32(const void* p) {
    uint32_t a;
    asm("{ .reg .u64 t; cvta.to.shared.u64 t, %1; cvt.u32.u64 %0, t; }" : "=r"(a) : "l"(p));
    return a;
}
__device__ __forceinline__ void ldsm4(uint32_t* r, uint32_t a) {
    asm volatile("ldmatrix.sync.aligned.m8n8.x4.shared.b16 {%0,%1,%2,%3}, [%4];"
        : "=r"(r[0]), "=r"(r[1]), "=r"(r[2]), "=r"(r[3]) : "r"(a));
}
__device__ __forceinline__ void ldsm4t(uint32_t* r, uint32_t a) {
    asm volatile("ldmatrix.sync.aligned.m8n8.x4.trans.shared.b16 {%0,%1,%2,%3}, [%4];"
        : "=r"(r[0]), "=r"(r[1]), "=r"(r[2]), "=r"(r[3]) : "r"(a));
}
__device__ __forceinline__ void mma16816(float* d, const uint32_t* a, uint32_t b0, uint32_t b1) {
    asm volatile("mma.sync.aligned.m16n8k16.row.col.f32.f16.f16.f32 "
        "{%0,%1,%2,%3}, {%4,%5,%6,%7}, {%8,%9}, {%0,%1,%2,%3};"
        : "+f"(d[0]), "+f"(d[1]), "+f"(d[2]), "+f"(d[3])
        : "r"(a[0]), "r"(a[1]), "r"(a[2]), "r"(a[3]), "r"(b0), "r"(b1));
}
// pack two f32 -> half2, then ex2 on both halves in ONE MUFU op
__device__ __forceinline__ uint32_t ex2p(float a, float b) {
    __half2 h = __floats2half2_rn(a, b);
    uint32_t x = *(uint32_t*)&h, r;
    asm("ex2.approx.f16x2 %0, %1;" : "=r"(r) : "r"(x));
    return r;
}

#define ONE2 0x3C003C00u   // half2 {1.0, 1.0}

// -------- kernel 1: Q (fp16, x log2e), K (fp16), V (fp16), norms, block max --------
__global__ void __launch_bounds__(128) qv_kernel(
    const float* __restrict__ inp, const float* __restrict__ W1,
    const float* __restrict__ b1,  const float* __restrict__ W2,
    const float* __restrict__ b2)
{
    __shared__ float Xs[32][32];
    __shared__ float W1s[16][32];
    __shared__ float W2s[32][32];
    __shared__ float b1s[16];
    __shared__ float b2s[32];
    __shared__ float Aq[32][16];

    int b  = blockIdx.x >> 8;
    int hw = blockIdx.x & 255;
    int tid = threadIdx.x;

    const float* ib = inp + (size_t)b * 262144 + hw * 32;
    for (int idx = tid; idx < 1024; idx += 128) {
        int l = idx >> 5, c = idx & 31;
        Xs[l][c] = ib[l * 8192 + c];
    }
    for (int idx = tid; idx < 512;  idx += 128) W1s[idx >> 5][idx & 31] = W1[idx];
    for (int idx = tid; idx < 1024; idx += 128) W2s[idx >> 5][idx & 31] = W2[idx];
    if (tid < 16) b1s[tid] = b1[tid];
    if (tid >= 32 && tid < 64) b2s[tid - 32] = b2[tid - 32];
    __syncthreads();

    // V[b, o*256+hw, c]
    for (int idx = tid; idx < 1024; idx += 128) {
        int o = idx >> 5, c = idx & 31;
        float s = b2s[o];
        #pragma unroll
        for (int l = 0; l < 32; l++) s += W2s[o][l] * Xs[l][c];
        g_Vh[b][o * 256 + hw][c] = __float2half(s);
    }
    // Q/K[b, i12*4096 + o*256 + hw, k]
    for (int idx = tid; idx < 512; idx += 128) {
        int o = idx >> 5, ch = idx & 31;
        float s = b1s[o];
        #pragma unroll
        for (int l = 0; l < 32; l++) s += W1s[o][l] * Xs[l][ch];
        int k = ch >> 1, i12 = ch & 1;
        int row = i12 * 4096 + o * 256 + hw;
        g_Qh[b][row][k] = __float2half(s * L2E);   // A side pre-scaled
        g_Kh[b][row][k] = __float2half(s);         // B side unscaled
        Aq[(o << 1) | i12][k] = s;
    }
    __syncthreads();

    if (tid < 32) {   // exactly warp 0
        int o = tid >> 1, i12 = tid & 1;
        float s = 0.f;
        #pragma unroll
        for (int k = 0; k < 16; k++) { float v = Aq[tid][k]; s += v * v; }
        g_Rn[b][i12 * 4096 + o * 256 + hw] = s;
        float m = s;
        #pragma unroll
        for (int off = 16; off; off >>= 1)
            m = fmaxf(m, __shfl_xor_sync(0xffffffffu, m, off));
        if (tid == 0) g_bmax[b][hw] = m;   // unconditional write: no reset kernel needed
    }
}

// -------- kernel 2: FA2-style fp16 mma.sync attention --------
// Fixed-shift softmax: m_hat_i = |Q_i| * max_j |Q_j| >= all logits (exact bound);
// shift applied via MMA accumulator init; exp via ex2.f16x2; row-sum via MMA with ones.
__global__ void __launch_bounds__(256, 1) attn3_kernel(
    const float* __restrict__ inp, const float* __restrict__ gamma,
    float* __restrict__ out)
{
    __shared__ __align__(16) __half Qs[BM * 16];        // 4 KB
    __shared__ __align__(16) __half Ks[2][BM * 16];     // 2x4 KB
    __shared__ __align__(16) __half Vs[2][BM * 32];     // 2x8 KB
    __shared__ float red[8];

    int tid = threadIdx.x, lane = tid & 31, wid = tid >> 5;
    int b = blockIdx.y;
    int i0 = blockIdx.x * BM;
    int wrow = wid * 16;

    // ---- preload Q tile and tile-0 K/V; fold in the 256-way max reduce ----
    float mv = g_bmax[b][tid];   // 256 threads, 256 entries
    {
        int r = tid >> 1, s = tid & 1;
        int sw = s ^ ((r >> 2) & 1);
        ((uint4*)Qs)[r * 2 + sw]    = *(const uint4*)&g_Qh[b][i0 + r][s * 8];
        ((uint4*)Ks[0])[r * 2 + sw] = *(const uint4*)&g_Kh[b][r][s * 8];
    }
    #pragma unroll
    for (int u = 0; u < 2; u++) {
        int e = tid + 256 * u;
        int r = e >> 2, s = e & 3;
        ((uint4*)Vs[0])[r * 4 + (s ^ ((r >> 1) & 3))] = *(const uint4*)&g_Vh[b][r][s * 8];
    }
    #pragma unroll
    for (int off = 16; off; off >>= 1)
        mv = fmaxf(mv, __shfl_xor_sync(0xffffffffu, mv, off));
    if (lane == 0) red[wid] = mv;
    __syncthreads();

    float msq = red[0];
    #pragma unroll
    for (int w = 1; w < 8; w++) msq = fmaxf(msq, red[w]);

    // ---- Q A-fragments (once) ----
    uint32_t qa[4];
    {
        int row = wrow + (lane & 7) + (lane & 8);
        int seg = lane >> 4;
        uint32_t a = smem_u32(Qs) + row * 32 + (seg ^ ((row >> 2) & 1)) * 16;
        ldsm4(qa, a);
    }

    int ia = i0 + wrow + (lane >> 2);
    float mh2a = L2E * sqrtf(g_Rn[b][ia] * msq);
    float mh2b = L2E * sqrtf(g_Rn[b][ia + 8] * msq);

    float Dc[16];
    #pragma unroll
    for (int t = 0; t < 16; t++) Dc[t] = 0.f;
    float Dl[4] = {0.f, 0.f, 0.f, 0.f};   // row-sum accumulator (all cols equal)
    uint32_t pA[8][4];

    uint32_t kbase0 = smem_u32(Ks[0]), kbase1 = smem_u32(Ks[1]);
    uint32_t vbase0 = smem_u32(Vs[0]), vbase1 = smem_u32(Vs[1]);

    for (int t = 0; t < NTILES; t++) {
        // prefetch next tile (gmem -> regs)
        uint4 kpre, vp0, vp1;
        if (t < NTILES - 1) {
            int jb2 = (t + 1) * BM;
            kpre = *(const uint4*)&g_Kh[b][jb2 + (tid >> 1)][(tid & 1) * 8];
            vp0  = *(const uint4*)&g_Vh[b][jb2 + (tid >> 2)][(tid & 3) * 8];
            int e = tid + 256;
            vp1  = *(const uint4*)&g_Vh[b][jb2 + (e >> 2)][(e & 3) * 8];
        }

        uint32_t kb = (t & 1) ? kbase1 : kbase0;
        uint32_t vb = (t & 1) ? vbase1 : vbase0;

        // ---- S = Q K^T, shift folded into accumulator init, exp in f16x2 ----
        #pragma unroll
        for (int np = 0; np < 8; np++) {
            uint32_t kf[4];
            {
                int row = np * 16 + (lane & 7) + ((lane >> 4) << 3);
                int seg = (lane >> 3) & 1;
                ldsm4(kf, kb + row * 32 + (seg ^ ((row >> 2) & 1)) * 16);
            }
            float s0[4] = {-mh2a, -mh2a, -mh2b, -mh2b};
            mma16816(s0, qa, kf[0], kf[1]);
            pA[np][0] = ex2p(s0[0], s0[1]);
            pA[np][1] = ex2p(s0[2], s0[3]);

            float s1[4] = {-mh2a, -mh2a, -mh2b, -mh2b};
            mma16816(s1, qa, kf[2], kf[3]);
            pA[np][2] = ex2p(s1[0], s1[1]);
            pA[np][3] = ex2p(s1[2], s1[3]);
        }

        // ---- D += P V ; row-sums += P * ones ----
        #pragma unroll
        for (int ks = 0; ks < 8; ks++) {
            mma16816(Dl, pA[ks], ONE2, ONE2);
            #pragma unroll
            for (int npair = 0; npair < 2; npair++) {
                uint32_t vf[4];
                {
                    int row = 16 * ks + (lane & 7) + (((lane >> 3) & 1) << 3);
                    int seg = npair * 2 + ((lane >> 4) & 1);
                    ldsm4t(vf, vb + row * 64 + (seg ^ ((row >> 1) & 3)) * 16);
                }
                mma16816(Dc + (2 * npair) * 4,     pA[ks], vf[0], vf[1]);
                mma16816(Dc + (2 * npair + 1) * 4, pA[ks], vf[2], vf[3]);
            }
        }

        // ---- stage next tile into the other buffer ----
        if (t < NTILES - 1) {
            int nxt = (t + 1) & 1;
            int r = tid >> 1, s = tid & 1;
            ((uint4*)Ks[nxt])[r * 2 + (s ^ ((r >> 2) & 1))] = kpre;
            r = tid >> 2; s = tid & 3;
            ((uint4*)Vs[nxt])[r * 4 + (s ^ ((r >> 1) & 3))] = vp0;
            int e = tid + 256;
            r = e >> 2; s = e & 3;
            ((uint4*)Vs[nxt])[r * 4 + (s ^ ((r >> 1) & 3))] = vp1;
        }
        __syncthreads();
    }

    // ---- normalize (row sums exact from MMA), residual, write ----
    float g = gamma[0];
    float ra = g / Dl[0], rb = g / Dl[2];
    size_t ba = (size_t)b * 262144 + (size_t)ia * 32;
    size_t bb = ba + 8 * 32;
    #pragma unroll
    for (int nt = 0; nt < 4; nt++) {
        int col = nt * 8 + (lane & 3) * 2;
        float2 iv = *(const float2*)(inp + ba + col);
        float2 ov;
        ov.x = Dc[nt * 4 + 0] * ra + iv.x;
        ov.y = Dc[nt * 4 + 1] * ra + iv.y;
        *(float2*)(out + ba + col) = ov;
        iv = *(const float2*)(inp + bb + col);
        ov.x = Dc[nt * 4 + 2] * rb + iv.x;
        ov.y = Dc[nt * 4 + 3] * rb + iv.y;
        *(float2*)(out + bb + col) = ov;
    }
}

extern "C" void kernel_launch(void* const* d_in, const int* in_sizes, int n_in,
                              void* d_out, int out_size) {
    const float* inp   = (const float*)d_in[0];
    const float* W1    = (const float*)d_in[1];
    const float* b1    = (const float*)d_in[2];
    const float* W2    = (const float*)d_in[3];
    const float* b2    = (const float*)d_in[4];
    const float* gamma = (const float*)d_in[5];
    float* out = (float*)d_out;

    qv_kernel<<<NB * 256, 128>>>(inp, W1, b1, W2, b2);
    attn3_kernel<<<dim3(NN / BM, NB), 256>>>(inp, gamma, out);
}